// round 15
// baseline (speedup 1.0000x reference)
#include <cuda_runtime.h>
#include <cuda_bf16.h>

#define BB 64
#define SS 512
#define HH 1024
#define TT 17

#define CONS 64
#define PROD 512
#define GRID (CONS + PROD)
#define ITEMS_PER_RANK 14                     // chunks 2..15 (0,1 self-made)
#define TOTAL_ITEMS (BB * ITEMS_PER_RANK)     // 896

typedef unsigned long long u64;

__device__ __forceinline__ u64 fma2(u64 a, u64 b, u64 c) {
    u64 d;
    asm("fma.rn.f32x2 %0, %1, %2, %3;" : "=l"(d) : "l"(a), "l"(b), "l"(c));
    return d;
}
__device__ __forceinline__ u64 add2(u64 a, u64 b) {
    u64 d;
    asm("add.rn.f32x2 %0, %1, %2;" : "=l"(d) : "l"(a), "l"(b));
    return d;
}
__device__ __forceinline__ u64 pack2(float lo, float hi) {
    u64 d;
    asm("mov.b64 %0, {%1, %2};" : "=l"(d) : "f"(lo), "f"(hi));
    return d;
}

__device__ int g_ticket;
__device__ int g_flag[BB * 16];   // [rank][chunk]

__global__ void zero_meta() {
    int i = blockIdx.x * blockDim.x + threadIdx.x;
    if (i == 0) g_ticket = 0;
    if (i < BB * 16) g_flag[i] = 0;
}

// ------------------- shared memory union (26.9 KB static) ------------------
// GEMM:  xs0 @0 (8704) | xs1 @8704 (8704) | wt0 @17408 (4624) | wt1 @22032 (4624)
// VIT:   bp @0 (8704)  | sc @8704 (160)      [used only after self-GEMM done]
// both:  rank_inv @26656 (256)  [persists]
#define SM_BYTES   26944
#define OFF_XS0    0
#define OFF_XS1    8704
#define OFF_WT0    17408
#define OFF_WT1    22032
#define OFF_BP     0
#define OFF_SC     8704
#define OFF_RINV   26656

#define ROWS_PB    32
#define KTILE      64
#define NKT        (HH / KTILE)
#define XS_STRIDE  68
#define WT_STRIDE  68

template<int T0, int CNT>
__device__ __forceinline__ void acc_tile(const float* __restrict__ xs_row,
                                         const float* __restrict__ wt, u64* acc)
{
#pragma unroll
    for (int c = 0; c < 16; c++) {
        ulonglong2 xv = *(const ulonglong2*)(xs_row + c * 4);
#pragma unroll
        for (int u = 0; u < CNT; u++) {
            ulonglong2 wv = *(const ulonglong2*)(wt + (T0 + u) * WT_STRIDE + c * 4);
            acc[u] = fma2(xv.x, wv.x, acc[u]);
            acc[u] = fma2(xv.y, wv.y, acc[u]);
        }
    }
}

// one 32-row x K=1024 chunk; all 128 threads participate.
__device__ void gemm_chunk(const float* __restrict__ x, const float* __restrict__ W,
                           const float* __restrict__ bias, float* __restrict__ feats,
                           int row0, char* smx, int tid)
{
    float* xsb[2] = { (float*)(smx + OFF_XS0), (float*)(smx + OFF_XS1) };
    float* wtb[2] = { (float*)(smx + OFF_WT0), (float*)(smx + OFF_WT1) };

    const int r = tid & 31;
    const int g = tid >> 5;          // warp = tag group (W LDS stay uniform)

    float4 px[4];
    float4 pw[3];

#pragma unroll
    for (int p = 0; p < 4; p++) {
        int idx = tid + p * 128;
        int rr = idx >> 4, cc = idx & 15;
        px[p] = *(const float4*)(x + (size_t)(row0 + rr) * HH + cc * 4);
    }
#pragma unroll
    for (int p = 0; p < 3; p++) {
        int idx = tid + p * 128;
        if (idx < TT * 16) {
            int t = idx >> 4, cc = idx & 15;
            pw[p] = *(const float4*)(W + (size_t)t * HH + cc * 4);
        }
    }

    u64 acc[5];
#pragma unroll
    for (int u = 0; u < 5; u++) acc[u] = 0ull;

#pragma unroll
    for (int p = 0; p < 4; p++) {
        int idx = tid + p * 128;
        int rr = idx >> 4, cc = idx & 15;
        *(float4*)&xsb[0][rr * XS_STRIDE + cc * 4] = px[p];
    }
#pragma unroll
    for (int p = 0; p < 3; p++) {
        int idx = tid + p * 128;
        if (idx < TT * 16) {
            int t = idx >> 4, cc = idx & 15;
            *(float4*)&wtb[0][t * WT_STRIDE + cc * 4] = pw[p];
        }
    }
    __syncthreads();

    for (int kt = 0; kt < NKT; kt++) {
        const int cur = kt & 1;

        if (kt + 1 < NKT) {
            const float* xk = x + (kt + 1) * KTILE;
#pragma unroll
            for (int p = 0; p < 4; p++) {
                int idx = tid + p * 128;
                int rr = idx >> 4, cc = idx & 15;
                px[p] = *(const float4*)(xk + (size_t)(row0 + rr) * HH + cc * 4);
            }
            const float* wk = W + (kt + 1) * KTILE;
#pragma unroll
            for (int p = 0; p < 3; p++) {
                int idx = tid + p * 128;
                if (idx < TT * 16) {
                    int t = idx >> 4, cc = idx & 15;
                    pw[p] = *(const float4*)(wk + (size_t)t * HH + cc * 4);
                }
            }
        }

        const float* xs_row = &xsb[cur][r * XS_STRIDE];
        if      (g == 0) acc_tile<0,  5>(xs_row, wtb[cur], acc);
        else if (g == 1) acc_tile<5,  4>(xs_row, wtb[cur], acc);
        else if (g == 2) acc_tile<9,  4>(xs_row, wtb[cur], acc);
        else             acc_tile<13, 4>(xs_row, wtb[cur], acc);

        if (kt + 1 < NKT) {
            const int nxt = cur ^ 1;
#pragma unroll
            for (int p = 0; p < 4; p++) {
                int idx = tid + p * 128;
                int rr = idx >> 4, cc = idx & 15;
                *(float4*)&xsb[nxt][rr * XS_STRIDE + cc * 4] = px[p];
            }
#pragma unroll
            for (int p = 0; p < 3; p++) {
                int idx = tid + p * 128;
                if (idx < TT * 16) {
                    int t = idx >> 4, cc = idx & 15;
                    *(float4*)&wtb[nxt][t * WT_STRIDE + cc * 4] = pw[p];
                }
            }
            __syncthreads();
        }
    }

    const int t0  = (g == 0) ? 0 : (g == 1) ? 5 : (g == 2) ? 9 : 13;
    const int cnt = (g == 0) ? 5 : 4;
    float* o = feats + (size_t)(row0 + r) * TT;
#pragma unroll
    for (int u = 0; u < 5; u++) {
        if (u < cnt) {
            float2 p = *(float2*)&acc[u];
            o[t0 + u] = p.x + p.y + bias[t0 + u];
        }
    }
}

// ---------------------------------------------------------------------------
// Fused kernel: blocks [0,64) = viterbi consumers (rank = blockIdx.x),
// blocks [64,576) = persistent GEMM producers pulling chunk-major tickets.
// ---------------------------------------------------------------------------
__global__ __launch_bounds__(128) void fused_kernel(
    const float* __restrict__ x, const float* __restrict__ W,
    const float* __restrict__ bias, const float* __restrict__ trans,
    const float* __restrict__ start_trans, const float* __restrict__ end_trans,
    const int* __restrict__ nwords, float* __restrict__ out_tags,
    float* __restrict__ feats)
{
    __shared__ __align__(16) char smx[SM_BYTES];
    int* rinv = (int*)(smx + OFF_RINV);           // rank -> batch
    int* stkt = rinv + BB;                        // ticket broadcast slot

    const int tid = threadIdx.x;

    // rank permutation (nw descending, ties by index); identical in all blocks
    if (tid < BB) {
        const int nwi = nwords[tid];
        int rk = 0;
        for (int j = 0; j < BB; j++) {
            const int nwj = nwords[j];
            rk += (nwj > nwi) || (nwj == nwi && j < tid);
        }
        rinv[rk] = tid;
    }
    __syncthreads();

    if (blockIdx.x >= CONS) {
        // ================= persistent producer =================
        while (true) {
            if (tid == 0) *stkt = atomicAdd(&g_ticket, 1);
            __syncthreads();
            const int it = *stkt;
            __syncthreads();
            if (it >= TOTAL_ITEMS) break;
            const int c = 2 + it / BB;           // chunk-major: all ranks' chunk c
            const int r = it % BB;
            const int batch = rinv[r];
            gemm_chunk(x, W, bias, feats, batch * SS + c * ROWS_PB, smx, tid);
            __threadfence();
            __syncthreads();
            if (tid == 0) atomicAdd(&g_flag[r * 16 + c], 1);
        }
        return;
    }

    // ================= viterbi consumer (rank = blockIdx.x) =================
    const int rank  = blockIdx.x;
    const int batch = rinv[rank];
    const int nw    = nwords[batch];

    // self-produce chunks 0 and 1 (rows 0..63) so the scan can start at once
    gemm_chunk(x, W, bias, feats, batch * SS + 0,       smx, tid);
    gemm_chunk(x, W, bias, feats, batch * SS + ROWS_PB, smx, tid);
    __syncthreads();

    if (tid >= 32) return;        // warps 1-3 done (exited threads satisfy bars)

    unsigned char* bp  = (unsigned char*)(smx + OFF_BP);
    float*         scp = (float*)(smx + OFF_SC);

    const int lane = tid;
    const int jj   = (lane < TT) ? lane : (TT - 1);

    float tcol[TT];
#pragma unroll
    for (int i = 0; i < TT; i++) tcol[i] = trans[i * TT + jj];
    u64 tc2[8];
#pragma unroll
    for (int p = 0; p < 8; p++) tc2[p] = pack2(tcol[2 * p], tcol[2 * p + 1]);
    const float tc16 = tcol[16];

    const float* fb = feats + (size_t)batch * SS * TT;
    const int fl0 = rank * 16;

    float score = start_trans[jj] + __ldg(fb + jj);     // t = 0
    if (lane < TT) scp[1 * 20 + jj] = score;
    __syncwarp();

    // 3-deep feats prefetch (rows 1..3 are in self-made chunk 0)
    float fA = __ldg(fb + 1 * TT + jj);
    float fB = __ldg(fb + 2 * TT + jj);
    float fC = __ldg(fb + 3 * TT + jj);

    for (int t = 1; t < nw; t++) {
        if ((t & 31) == 0) {                  // gate next chunk (covers +3 reads)
            int cg = (t >> 5) + 1; if (cg > 15) cg = 15;
            if (lane == 0) {
                int v;
                do {
                    asm volatile("ld.acquire.gpu.global.b32 %0, [%1];"
                                 : "=r"(v) : "l"(&g_flag[fl0 + cg]) : "memory");
                    if (!v) __nanosleep(100);
                } while (!v);
            }
            __syncwarp();
        }

        const float* s = scp + (t & 1) * 20;

        ulonglong2 sA = *(const ulonglong2*)(s);
        ulonglong2 sB = *(const ulonglong2*)(s + 4);
        ulonglong2 sC = *(const ulonglong2*)(s + 8);
        ulonglong2 sD = *(const ulonglong2*)(s + 12);
        float s16 = s[16];

        u64 c2[8];
        c2[0] = add2(sA.x, tc2[0]); c2[1] = add2(sA.y, tc2[1]);
        c2[2] = add2(sB.x, tc2[2]); c2[3] = add2(sB.y, tc2[3]);
        c2[4] = add2(sC.x, tc2[4]); c2[5] = add2(sC.y, tc2[5]);
        c2[6] = add2(sD.x, tc2[6]); c2[7] = add2(sD.y, tc2[7]);
        float c16 = s16 + tc16;

        float c[16];
#pragma unroll
        for (int p = 0; p < 8; p++) {
            float2 cp = *(float2*)&c2[p];
            c[2 * p] = cp.x; c[2 * p + 1] = cp.y;
        }

        float m8[8];
#pragma unroll
        for (int p = 0; p < 8; p++) m8[p] = fmaxf(c[2 * p], c[2 * p + 1]);
        float m4[4];
#pragma unroll
        for (int p = 0; p < 4; p++) m4[p] = fmaxf(m8[2 * p], m8[2 * p + 1]);
        float bv = fmaxf(fmaxf(fmaxf(m4[0], m4[1]), fmaxf(m4[2], m4[3])), c16);

        score = bv + fA;
        fA = fB; fB = fC;
        {
            int tp = t + 3; if (tp > SS - 1) tp = SS - 1;
            fC = __ldg(fb + tp * TT + jj);
        }
        if (lane < TT) scp[((t + 1) & 1) * 20 + jj] = score;
        __syncwarp();

        int e[16];
#pragma unroll
        for (int i = 0; i < 16; i++) e[i] = (c[i] == bv) ? i : 31;
        int e16 = (c16 == bv) ? 16 : 31;
        int i8[8];
#pragma unroll
        for (int p = 0; p < 8; p++) i8[p] = min(e[2 * p], e[2 * p + 1]);
        int i4[4];
#pragma unroll
        for (int p = 0; p < 4; p++) i4[p] = min(i8[2 * p], i8[2 * p + 1]);
        int bi = min(min(min(i4[0], i4[1]), min(i4[2], i4[3])), e16);

        if (lane < TT) bp[t * TT + jj] = (unsigned char)bi;
    }

    __syncwarp();

    float* o = out_tags + (size_t)batch * SS;
    for (int t = nw + lane; t < SS; t += 32) o[t] = 0.0f;   // masked tail

    if (lane == 0) {
        const float* s = scp + (nw & 1) * 20;
        int cur = 0;
        float bv = s[0] + end_trans[0];
#pragma unroll
        for (int i = 1; i < TT; i++) {
            float v = s[i] + end_trans[i];
            if (v > bv) { bv = v; cur = i; }
        }
        for (int t = nw - 1; t >= 1; t--) {
            o[t] = (float)cur;
            cur = bp[t * TT + cur];
        }
        o[0] = (float)cur;      // nwords >= 1
    }
}

// ---------------------------------------------------------------------------
// Inputs: x, W, b, transitions, start_trans, end_trans, nwords
// Output: [padded_tags (B*S) | feats (B*S*T)] float32
// ---------------------------------------------------------------------------
extern "C" void kernel_launch(void* const* d_in, const int* in_sizes, int n_in,
                              void* d_out, int out_size)
{
    const float* x     = (const float*)d_in[0];
    const float* W     = (const float*)d_in[1];
    const float* bias  = (const float*)d_in[2];
    const float* trans = (const float*)d_in[3];
    const float* st    = (const float*)d_in[4];
    const float* en    = (const float*)d_in[5];
    const int*   nw    = (const int*)d_in[6];

    float* out   = (float*)d_out;
    float* tags  = out;                // B*S
    float* feats = out + BB * SS;      // B*S*T

    zero_meta<<<8, 128>>>();
    fused_kernel<<<GRID, 128>>>(x, W, bias, trans, st, en, nw, tags, feats);
}

// round 16
// speedup vs baseline: 1.6835x; 1.6835x over previous
#include <cuda_runtime.h>
#include <cuda_bf16.h>

#define BB 64
#define SS 512
#define HH 1024
#define TT 17

typedef unsigned long long u64;

__device__ __forceinline__ u64 fma2(u64 a, u64 b, u64 c) {
    u64 d;
    asm("fma.rn.f32x2 %0, %1, %2, %3;" : "=l"(d) : "l"(a), "l"(b), "l"(c));
    return d;
}
__device__ __forceinline__ u64 add2(u64 a, u64 b) {
    u64 d;
    asm("add.rn.f32x2 %0, %1, %2;" : "=l"(d) : "l"(a), "l"(b));
    return d;
}
__device__ __forceinline__ u64 pack2(float lo, float hi) {
    u64 d;
    asm("mov.b64 %0, {%1, %2};" : "=l"(d) : "f"(lo), "f"(hi));
    return d;
}

// ---------------------------------------------------------------------------
// GEMM: feats[r][t] = sum_h x[r][h]*W[t][h] + b[t]  (M=32768, K=1024, N=17)
// x is NOT staged in smem (that round trip was the crossbar bottleneck:
// ~9.4M phases). Warp = 8 rows: thread (r,s) owns rows {2r,2r+1}, k striped
// by s (k-chunk j*32 + s*4). x LDG is coalesced (lanes s consecutive 16B).
// Only W lives in smem (two 34 KB K-halves); wt LDS is one conflict-free
// 128B phase (s spans banks 0-31, 4 r-copies broadcast). Butterfly-shfl
// reduction over s at the end. Packed fma.rn.f32x2 throughout.
// ---------------------------------------------------------------------------
#define GT      128
#define KH      512                 // K half
#define ROWS_PB 32                  // 4 warps x 8 rows

__global__ __launch_bounds__(GT, 4) void gemm_feats(
    const float* __restrict__ x, const float* __restrict__ W,
    const float* __restrict__ bias, float* __restrict__ feats)
{
    __shared__ float wslab[TT * KH];        // 34816 B

    const int tid  = threadIdx.x;
    const int wid  = tid >> 5;
    const int lane = tid & 31;
    const int r    = lane >> 3;             // 0..3 (row pair)
    const int s    = lane & 7;              // 0..7 (k stripe)
    const int rowA = blockIdx.x * ROWS_PB + wid * 8 + r * 2;

    const float* xA = x + (size_t)rowA * HH;
    const float* xB = xA + HH;

    u64 accA[TT], accB[TT];
#pragma unroll
    for (int t = 0; t < TT; t++) { accA[t] = 0ull; accB[t] = 0ull; }

    for (int h = 0; h < 2; h++) {
        __syncthreads();   // previous half's reads done before overwrite
        // stage W half-slab [17 x 512]: 2176 float4, coalesced
        for (int i = tid; i < TT * (KH / 4); i += GT) {
            int t = i >> 7;           // 128 float4 per tag
            int c = i & 127;
            *(float4*)&wslab[t * KH + c * 4] =
                *(const float4*)(W + (size_t)t * HH + h * KH + c * 4);
        }
        __syncthreads();

        const float* xAh = xA + h * KH;
        const float* xBh = xB + h * KH;

        float4 a0 = *(const float4*)(xAh + s * 4);
        float4 b0 = *(const float4*)(xBh + s * 4);

        for (int j = 0; j < 16; j++) {
            float4 a1 = a0, b1 = b0;
            if (j < 15) {
                a1 = *(const float4*)(xAh + (j + 1) * 32 + s * 4);
                b1 = *(const float4*)(xBh + (j + 1) * 32 + s * 4);
            }

            ulonglong2 xa = *(ulonglong2*)&a0;
            ulonglong2 xb = *(ulonglong2*)&b0;
            const float* wj = wslab + j * 32 + s * 4;
#pragma unroll
            for (int t = 0; t < TT; t++) {
                ulonglong2 wv = *(const ulonglong2*)(wj + t * KH);
                accA[t] = fma2(xa.x, wv.x, accA[t]);
                accA[t] = fma2(xa.y, wv.y, accA[t]);
                accB[t] = fma2(xb.x, wv.x, accB[t]);
                accB[t] = fma2(xb.y, wv.y, accB[t]);
            }
            a0 = a1; b0 = b1;
        }
    }

    // butterfly reduction over the 8 k-stripes (lane bits 0..2)
#pragma unroll
    for (int t = 0; t < TT; t++) {
#pragma unroll
        for (int m = 1; m <= 4; m <<= 1) {
            accA[t] = add2(accA[t], __shfl_xor_sync(0xffffffffu, accA[t], m));
            accB[t] = add2(accB[t], __shfl_xor_sync(0xffffffffu, accB[t], m));
        }
    }

    // every s-lane holds the full sums; distribute stores t = s, s+8, (s==0:16)
    float* oA = feats + (size_t)rowA * TT;   // rowB = rowA+1 => offset +TT
    for (int t = s; t < TT; t += 8) {
        float2 pa = *(float2*)&accA[t];
        float2 pb = *(float2*)&accB[t];
        float bs = bias[t];
        oA[t]      = pa.x + pa.y + bs;
        oA[TT + t] = pb.x + pb.y + bs;
    }
}

// ---------------------------------------------------------------------------
// Viterbi (R13, measured 68.5us): one block per batch, producer/consumer
// warp split; warp0 = score recurrence, warp1 = backpointer/argmax one
// 8-step phase behind via score+bv rings; named barrier per phase.
// ---------------------------------------------------------------------------
__global__ __launch_bounds__(128) void viterbi_kernel(
    const float* __restrict__ feats, const float* __restrict__ trans,
    const float* __restrict__ start_trans, const float* __restrict__ end_trans,
    const int* __restrict__ nwords, float* __restrict__ out_tags)
{
    __shared__ float fs[SS * TT];                    // 34816 B
    __shared__ unsigned char bp[SS * TT];            //  8704 B
    __shared__ __align__(16) float sch[32][20];      //  score ring
    __shared__ __align__(16) float bvh[32][20];      //  bv ring

    const int b   = blockIdx.x;
    const int tid = threadIdx.x;
    const int nw  = nwords[b];

    const float4* fb4 = (const float4*)(feats + (size_t)b * SS * TT);
    const int n4 = (nw * TT + 3) >> 2;
    for (int i = tid; i < n4; i += 128)
        ((float4*)fs)[i] = fb4[i];
    __syncthreads();

    if (tid >= 64) return;          // warps 2,3 done

    const int wid  = tid >> 5;
    const int lane = tid & 31;
    const int jj   = (lane < TT) ? lane : (TT - 1);

    float tcol[TT];
#pragma unroll
    for (int i = 0; i < TT; i++) tcol[i] = trans[i * TT + jj];
    u64 tc2[8];
#pragma unroll
    for (int p = 0; p < 8; p++) tc2[p] = pack2(tcol[2 * p], tcol[2 * p + 1]);
    const float tc16 = tcol[16];

    if (wid == 0) {
        float s0 = start_trans[jj] + fs[jj];
        if (lane < TT) sch[0][jj] = s0;
        __syncwarp();
    }

    const int np = (nw - 1 + 7) >> 3;

    for (int p = 0; p <= np; p++) {
        if (wid == 0 && p < np) {
            const int t0 = 1 + p * 8;
            const int t1 = min(t0 + 8, nw);
            for (int t = t0; t < t1; t++) {
                const float f = fs[t * TT + jj];
                const float* s = sch[(t - 1) & 31];
                ulonglong2 sA = *(const ulonglong2*)(s);
                ulonglong2 sB = *(const ulonglong2*)(s + 4);
                ulonglong2 sC = *(const ulonglong2*)(s + 8);
                ulonglong2 sD = *(const ulonglong2*)(s + 12);
                float s16 = s[16];

                u64 c2[8];
                c2[0] = add2(sA.x, tc2[0]); c2[1] = add2(sA.y, tc2[1]);
                c2[2] = add2(sB.x, tc2[2]); c2[3] = add2(sB.y, tc2[3]);
                c2[4] = add2(sC.x, tc2[4]); c2[5] = add2(sC.y, tc2[5]);
                c2[6] = add2(sD.x, tc2[6]); c2[7] = add2(sD.y, tc2[7]);
                float c16 = s16 + tc16;

                float c[16];
#pragma unroll
                for (int q = 0; q < 8; q++) {
                    float2 cp = *(float2*)&c2[q];
                    c[2 * q] = cp.x; c[2 * q + 1] = cp.y;
                }
                float m8[8];
#pragma unroll
                for (int q = 0; q < 8; q++) m8[q] = fmaxf(c[2 * q], c[2 * q + 1]);
                float m4[4];
#pragma unroll
                for (int q = 0; q < 4; q++) m4[q] = fmaxf(m8[2 * q], m8[2 * q + 1]);
                float bv = fmaxf(fmaxf(fmaxf(m4[0], m4[1]), fmaxf(m4[2], m4[3])), c16);

                float sn = bv + f;
                if (lane < TT) {
                    sch[t & 31][jj] = sn;
                    bvh[t & 31][jj] = bv;
                }
                __syncwarp();
            }
        }
        if (wid == 1 && p > 0) {
            const int t0 = 1 + (p - 1) * 8;
            const int t1 = min(t0 + 8, nw);
            for (int t = t0; t < t1; t++) {
                const float* s = sch[(t - 1) & 31];
                ulonglong2 sA = *(const ulonglong2*)(s);
                ulonglong2 sB = *(const ulonglong2*)(s + 4);
                ulonglong2 sC = *(const ulonglong2*)(s + 8);
                ulonglong2 sD = *(const ulonglong2*)(s + 12);
                float s16 = s[16];
                float bv  = bvh[t & 31][jj];

                u64 c2[8];
                c2[0] = add2(sA.x, tc2[0]); c2[1] = add2(sA.y, tc2[1]);
                c2[2] = add2(sB.x, tc2[2]); c2[3] = add2(sB.y, tc2[3]);
                c2[4] = add2(sC.x, tc2[4]); c2[5] = add2(sC.y, tc2[5]);
                c2[6] = add2(sD.x, tc2[6]); c2[7] = add2(sD.y, tc2[7]);
                float c16 = s16 + tc16;

                float c[16];
#pragma unroll
                for (int q = 0; q < 8; q++) {
                    float2 cp = *(float2*)&c2[q];
                    c[2 * q] = cp.x; c[2 * q + 1] = cp.y;
                }
                int e[16];
#pragma unroll
                for (int i = 0; i < 16; i++) e[i] = (c[i] == bv) ? i : 31;
                int e16 = (c16 == bv) ? 16 : 31;
                int i8[8];
#pragma unroll
                for (int q = 0; q < 8; q++) i8[q] = min(e[2 * q], e[2 * q + 1]);
                int i4[4];
#pragma unroll
                for (int q = 0; q < 4; q++) i4[q] = min(i8[2 * q], i8[2 * q + 1]);
                int bi = min(min(min(i4[0], i4[1]), min(i4[2], i4[3])), e16);

                if (lane < TT) bp[t * TT + jj] = (unsigned char)bi;
            }
        }
        asm volatile("bar.sync 1, 64;" ::: "memory");
    }

    if (wid == 0) {
        float* o = out_tags + (size_t)b * SS;
        for (int t = nw + lane; t < SS; t += 32) o[t] = 0.0f;

        if (lane == 0) {
            const float* s = sch[(nw - 1) & 31];
            int cur = 0;
            float bv = s[0] + end_trans[0];
#pragma unroll
            for (int i = 1; i < TT; i++) {
                float v = s[i] + end_trans[i];
                if (v > bv) { bv = v; cur = i; }
            }
            for (int t = nw - 1; t >= 1; t--) {
                o[t] = (float)cur;
                cur = bp[t * TT + cur];
            }
            o[0] = (float)cur;   // nwords >= 1
        }
    }
}

// ---------------------------------------------------------------------------
// Inputs: x, W, b, transitions, start_trans, end_trans, nwords
// Output: [padded_tags (B*S) | feats (B*S*T)] float32
// ---------------------------------------------------------------------------
extern "C" void kernel_launch(void* const* d_in, const int* in_sizes, int n_in,
                              void* d_out, int out_size)
{
    const float* x     = (const float*)d_in[0];
    const float* W     = (const float*)d_in[1];
    const float* bias  = (const float*)d_in[2];
    const float* trans = (const float*)d_in[3];
    const float* st    = (const float*)d_in[4];
    const float* en    = (const float*)d_in[5];
    const int*   nw    = (const int*)d_in[6];

    float* out   = (float*)d_out;
    float* tags  = out;                // B*S
    float* feats = out + BB * SS;      // B*S*T

    gemm_feats<<<(BB * SS) / ROWS_PB, GT>>>(x, W, bias, feats);
    viterbi_kernel<<<BB, 128>>>(feats, trans, st, en, nw, tags);
}